// round 1
// baseline (speedup 1.0000x reference)
#include <cuda_runtime.h>
#include <cuda_bf16.h>
#include <math.h>

#define BB   64
#define LL   65536
#define NW   2047
#define WPB  128      // windows per block
#define BPB  16       // blocks per batch  (16*128 >= 2047)
#define SPAN_MAX 4128
#define HID  512
#define DM   256
#define SD   321      // 256 + 1 + 64

// ---------------- scratch (no allocation allowed; __device__ globals) -------
__device__ unsigned int g_hist_parts[BB * BPB * 256];  // per-block partial hists
__device__ float g_went[BB * NW];
__device__ float g_feats[BB * SD];
__device__ float g_z1[BB * HID];
__device__ float g_z2[BB * HID];

// ---------------- Kernel A: windowed entropies + global hist partials -------
__global__ void __launch_bounds__(256) win_kernel(const int* __restrict__ x) {
    const int b    = blockIdx.y;
    const int blk  = blockIdx.x;
    const int tid  = threadIdx.x;
    const int lane = tid & 31;
    const int warp = tid >> 5;

    const int wstart = blk * WPB;
    const int wcount = min(WPB, NW - wstart);          // 128 (or 127 last block)
    const int span   = (wcount - 1) * 32 + 64;         // 4128 or 4096
    const long base  = (long)b * LL + (long)blk * (WPB * 32);

    __shared__ unsigned char s_x[SPAN_MAX + 32];
    __shared__ unsigned int  s_hist[8][256];
    __shared__ unsigned int  s_part[256];
    __shared__ float         s_lut[65];   // term(c)/c so H = sum over elements

    if (tid < 256) s_part[tid] = 0u;
    if (tid <= 64) {
        if (tid == 0) s_lut[0] = 0.0f;
        else {
            float p = (float)tid * (1.0f / 64.0f);          // c/64, exact
            float t = -(p * log2f(p + 1e-10f));             // matches reference fp32
            s_lut[tid] = t / (float)tid;
        }
    }
    for (int i = tid; i < span; i += 256) {
        int v = x[base + i];
        v = v < 0 ? 0 : (v > 255 ? 255 : v);
        s_x[i] = (unsigned char)v;
    }
    __syncthreads();

    // global histogram over this block's owned 4096 bytes
    for (int i = tid; i < 4096; i += 256)
        atomicAdd(&s_part[s_x[i]], 1u);

    unsigned int* hist = s_hist[warp];
    for (int wi = warp; wi < wcount; wi += 8) {
        const int off = wi * 32;
        #pragma unroll
        for (int j = 0; j < 8; j++) hist[lane + 32 * j] = 0u;
        __syncwarp();
        const int va = s_x[off + lane];
        const int vb = s_x[off + 32 + lane];
        atomicAdd(&hist[va], 1u);
        atomicAdd(&hist[vb], 1u);
        __syncwarp();
        float h = s_lut[hist[va]] + s_lut[hist[vb]];
        #pragma unroll
        for (int o = 16; o; o >>= 1) h += __shfl_xor_sync(0xffffffffu, h, o);
        if (lane == 0) g_went[b * NW + wstart + wi] = h;
    }

    __syncthreads();
    if (tid < 256) g_hist_parts[(b * BPB + blk) * 256 + tid] = s_part[tid];
}

// ---------------- Kernel B: features (hist, global entropy, CDF) ------------
__global__ void __launch_bounds__(256) feat_kernel() {
    const int b = blockIdx.x;
    const int tid = threadIdx.x;

    __shared__ float        s_red[256];
    __shared__ float        s_lev[64];
    __shared__ unsigned int s_cnt[64];

    float term = 0.0f;
    {
        unsigned int c = 0;
        #pragma unroll
        for (int p = 0; p < BPB; p++)
            c += g_hist_parts[(b * BPB + p) * 256 + tid];
        float nh = (float)c * (1.0f / 65536.0f);   // / (L + 1e-10) == /65536 in fp32
        g_feats[b * SD + tid] = nh;
        term = -(nh * log2f(nh + 1e-10f));
    }
    s_red[tid] = term;
    if (tid < 64) {
        s_lev[tid] = (tid == 63) ? 8.0f : (float)tid * (8.0f / 63.0f);
        s_cnt[tid] = 0u;
    }
    __syncthreads();

    for (int s = 128; s; s >>= 1) {
        if (tid < s) s_red[tid] += s_red[tid + s];
        __syncthreads();
    }
    if (tid == 0) g_feats[b * SD + 256] = s_red[0];

    for (int i = tid; i < NW; i += 256) {
        float h = g_went[b * NW + i];
        int lo = 0, hi = 63;                 // first j with h <= lev[j]
        while (lo < hi) {
            int mid = (lo + hi) >> 1;
            if (h <= s_lev[mid]) hi = mid; else lo = mid + 1;
        }
        atomicAdd(&s_cnt[lo], 1u);
    }
    __syncthreads();
    if (tid < 64) {
        unsigned int sum = 0;
        for (int k = 0; k <= tid; k++) sum += s_cnt[k];
        g_feats[b * SD + 257 + tid] = (float)sum / 2047.0f;
    }
}

// ---------------- Kernel C: Z1 = feats @ W1 + b1 ----------------------------
__global__ void __launch_bounds__(256) gemm1_kernel(const float* __restrict__ W1,
                                                    const float* __restrict__ b1) {
    const int tid = threadIdx.x;
    const int c   = blockIdx.x * 64 + (tid & 63);
    const int r0  = blockIdx.y * 8;
    const int ty  = tid >> 6;                 // 0..3 -> rows ty, ty+4

    __shared__ float s_a[8][SD];
    for (int i = tid; i < 8 * SD; i += 256) {
        int r = i / SD, k = i - r * SD;
        s_a[r][k] = g_feats[(r0 + r) * SD + k];
    }
    __syncthreads();

    float acc0 = 0.0f, acc1 = 0.0f;
    const float* w = W1 + c;
    #pragma unroll 4
    for (int k = 0; k < SD; k++) {
        float wv = w[k * HID];
        acc0 = fmaf(s_a[ty][k],     wv, acc0);
        acc1 = fmaf(s_a[ty + 4][k], wv, acc1);
    }
    float bv = b1[c];
    g_z1[(r0 + ty) * HID + c]     = acc0 + bv;
    g_z1[(r0 + ty + 4) * HID + c] = acc1 + bv;
}

// ---------------- Kernels D/E: out = relu(LN(Zin)) @ W + bias ---------------
// LAYER==2: Zin=g_z1 -> g_z2 (N=512).  LAYER==3: Zin=g_z2 -> out (N=256).
template <int LAYER>
__global__ void __launch_bounds__(256) ln_gemm_kernel(const float* __restrict__ g,
                                                      const float* __restrict__ be,
                                                      const float* __restrict__ W,
                                                      const float* __restrict__ bias,
                                                      float* __restrict__ out3) {
    constexpr int N = (LAYER == 2) ? 512 : 256;
    const float* Zin  = (LAYER == 2) ? g_z1 : g_z2;
    float*       Zout = (LAYER == 2) ? g_z2 : out3;

    const int tid  = threadIdx.x;
    const int lane = tid & 31;
    const int warp = tid >> 5;                 // one warp per row
    const int c    = blockIdx.x * 64 + (tid & 63);
    const int r0   = blockIdx.y * 8;

    __shared__ float s_a[8][HID];
    {
        const float* zr = Zin + (r0 + warp) * HID;
        float v[16];
        float sum = 0.0f;
        #pragma unroll
        for (int i = 0; i < 16; i++) { v[i] = zr[lane + 32 * i]; sum += v[i]; }
        #pragma unroll
        for (int o = 16; o; o >>= 1) sum += __shfl_xor_sync(0xffffffffu, sum, o);
        float mu = sum * (1.0f / 512.0f);
        float vs = 0.0f;
        #pragma unroll
        for (int i = 0; i < 16; i++) { float d = v[i] - mu; vs += d * d; }
        #pragma unroll
        for (int o = 16; o; o >>= 1) vs += __shfl_xor_sync(0xffffffffu, vs, o);
        float rstd = rsqrtf(vs * (1.0f / 512.0f) + 1e-5f);
        #pragma unroll
        for (int i = 0; i < 16; i++) {
            int k = lane + 32 * i;
            float hv = (v[i] - mu) * rstd * g[k] + be[k];
            s_a[warp][k] = fmaxf(hv, 0.0f);
        }
    }
    __syncthreads();

    float acc0 = 0.0f, acc1 = 0.0f;
    const int ty = tid >> 6;
    const float* w = W + c;
    #pragma unroll 4
    for (int k = 0; k < HID; k++) {
        float wv = w[k * N];
        acc0 = fmaf(s_a[ty][k],     wv, acc0);
        acc1 = fmaf(s_a[ty + 4][k], wv, acc1);
    }
    float bv = bias[c];
    Zout[(r0 + ty) * N + c]     = acc0 + bv;
    Zout[(r0 + ty + 4) * N + c] = acc1 + bv;
}

// ---------------- launch ----------------------------------------------------
extern "C" void kernel_launch(void* const* d_in, const int* in_sizes, int n_in,
                              void* d_out, int out_size) {
    const int*   x   = (const int*)d_in[0];
    const float* W1  = (const float*)d_in[1];
    const float* b1  = (const float*)d_in[2];
    const float* g1  = (const float*)d_in[3];
    const float* be1 = (const float*)d_in[4];
    const float* W2  = (const float*)d_in[5];
    const float* b2  = (const float*)d_in[6];
    const float* g2  = (const float*)d_in[7];
    const float* be2 = (const float*)d_in[8];
    const float* W3  = (const float*)d_in[9];
    const float* b3  = (const float*)d_in[10];
    float* out = (float*)d_out;

    win_kernel<<<dim3(BPB, BB), 256>>>(x);
    feat_kernel<<<BB, 256>>>();
    gemm1_kernel<<<dim3(HID / 64, BB / 8), 256>>>(W1, b1);
    ln_gemm_kernel<2><<<dim3(HID / 64, BB / 8), 256>>>(g1, be1, W2, b2, nullptr);
    ln_gemm_kernel<3><<<dim3(DM / 64, BB / 8), 256>>>(g2, be2, W3, b3, out);
}

// round 2
// speedup vs baseline: 1.8229x; 1.8229x over previous
#include <cuda_runtime.h>
#include <cuda_bf16.h>
#include <math.h>

#define BB   64
#define LL   65536
#define NW   2047
#define WPB  128      // windows per block
#define BPB  16       // blocks per batch
#define SPAN_MAX 4128
#define HID  512
#define DM   256
#define SD   321      // 256 + 1 + 64

// ---------------- scratch (__device__ globals; no allocation allowed) -------
__device__ unsigned int g_hist_parts[BB * BPB * 256];
__device__ float g_went[BB * NW];
__device__ float g_feats[BB * SD];
__device__ float g_z1[BB * HID];
__device__ float g_z2[BB * HID];

// ---------------- Kernel A: windowed entropies + global hist partials -------
__global__ void __launch_bounds__(256) win_kernel(const int* __restrict__ x) {
    const int b    = blockIdx.y;
    const int blk  = blockIdx.x;
    const int tid  = threadIdx.x;
    const int lane = tid & 31;
    const int warp = tid >> 5;

    const int wstart = blk * WPB;
    const int wcount = min(WPB, NW - wstart);          // 128 (or 127 last block)
    const int span   = (wcount - 1) * 32 + 64;         // 4128 or 4096
    const long base  = (long)b * LL + (long)blk * (WPB * 32);

    __shared__ __align__(16) unsigned char s_x[SPAN_MAX + 32];
    __shared__ unsigned int  s_hist[8][256];
    __shared__ unsigned int  s_part[256];
    __shared__ float         s_lut[65];

    if (tid < 256) s_part[tid] = 0u;
    if (tid <= 64) {
        if (tid == 0) s_lut[0] = 0.0f;
        else {
            float p = (float)tid * (1.0f / 64.0f);          // c/64, exact
            float t = -(p * log2f(p + 1e-10f));             // matches reference fp32
            s_lut[tid] = t / (float)tid;
        }
    }
    // vectorized byte load: int4 -> uchar4
    {
        const int4* xv = (const int4*)(x + base);
        uchar4* sv = (uchar4*)s_x;
        const int n4 = span >> 2;
        for (int i = tid; i < n4; i += 256) {
            int4 v = xv[i];
            int a0 = min(max(v.x, 0), 255);
            int a1 = min(max(v.y, 0), 255);
            int a2 = min(max(v.z, 0), 255);
            int a3 = min(max(v.w, 0), 255);
            sv[i] = make_uchar4((unsigned char)a0, (unsigned char)a1,
                                (unsigned char)a2, (unsigned char)a3);
        }
    }
    __syncthreads();

    // global histogram over this block's owned 4096 bytes
    for (int i = tid; i < 4096; i += 256)
        atomicAdd(&s_part[s_x[i]], 1u);

    unsigned int* hist = s_hist[warp];
    for (int wi = warp; wi < wcount; wi += 8) {
        const int off = wi * 32;
        #pragma unroll
        for (int j = 0; j < 8; j++) hist[lane + 32 * j] = 0u;
        __syncwarp();
        const int va = s_x[off + lane];
        const int vb = s_x[off + 32 + lane];
        atomicAdd(&hist[va], 1u);
        atomicAdd(&hist[vb], 1u);
        __syncwarp();
        float h = s_lut[hist[va]] + s_lut[hist[vb]];
        #pragma unroll
        for (int o = 16; o; o >>= 1) h += __shfl_xor_sync(0xffffffffu, h, o);
        if (lane == 0) g_went[b * NW + wstart + wi] = h;
    }

    __syncthreads();
    if (tid < 256) g_hist_parts[(b * BPB + blk) * 256 + tid] = s_part[tid];
}

// ---------------- Kernel B: features (hist, global entropy, CDF) ------------
__global__ void __launch_bounds__(256) feat_kernel() {
    const int b = blockIdx.x;
    const int tid = threadIdx.x;

    __shared__ float        s_red[256];
    __shared__ float        s_lev[64];
    __shared__ unsigned int s_cnt[64];

    float term = 0.0f;
    {
        unsigned int c = 0;
        #pragma unroll
        for (int p = 0; p < BPB; p++)
            c += g_hist_parts[(b * BPB + p) * 256 + tid];
        float nh = (float)c * (1.0f / 65536.0f);
        g_feats[b * SD + tid] = nh;
        term = -(nh * log2f(nh + 1e-10f));
    }
    s_red[tid] = term;
    if (tid < 64) {
        s_lev[tid] = (tid == 63) ? 8.0f : (float)tid * (8.0f / 63.0f);
        s_cnt[tid] = 0u;
    }
    __syncthreads();

    for (int s = 128; s; s >>= 1) {
        if (tid < s) s_red[tid] += s_red[tid + s];
        __syncthreads();
    }
    if (tid == 0) g_feats[b * SD + 256] = s_red[0];

    for (int i = tid; i < NW; i += 256) {
        float h = g_went[b * NW + i];
        int lo = 0, hi = 63;
        while (lo < hi) {
            int mid = (lo + hi) >> 1;
            if (h <= s_lev[mid]) hi = mid; else lo = mid + 1;
        }
        atomicAdd(&s_cnt[lo], 1u);
    }
    __syncthreads();
    if (tid < 64) {
        unsigned int sum = 0;
        for (int k = 0; k <= tid; k++) sum += s_cnt[k];
        g_feats[b * SD + 257 + tid] = (float)sum / 2047.0f;
    }
}

// ---------------- Tiled MLP GEMMs ------------------------------------------
// MODE 1: z1 = feats @ W1 + b1                (K=321 pad 384, N=512)
// MODE 2: z2 = relu(LN(z1)) @ W2 + b2         (K=512, N=512)
// MODE 3: out = relu(LN(z2)) @ W3 + b3        (K=512, N=256)
// Block: 256 threads, output tile 8 rows x 32 cols, K chunked by 64,
// W chunks double-buffered through shared memory.
template <int MODE>
__global__ void __launch_bounds__(256) mlp_kernel(const float* __restrict__ g,
                                                  const float* __restrict__ be,
                                                  const float* __restrict__ W,
                                                  const float* __restrict__ bias,
                                                  float* __restrict__ outp) {
    constexpr int KP = (MODE == 1) ? 384 : 512;
    constexpr int NC = KP / 64;
    constexpr int N  = (MODE == 3) ? DM : HID;

    const int tid  = threadIdx.x;
    const int row  = tid >> 5;
    const int col  = tid & 31;
    const int c0   = blockIdx.x * 32;
    const int r0   = blockIdx.y * 8;

    __shared__ float s_a[8][KP];
    __shared__ float s_w[2][64][32];

    // ---- stage A (8 rows) ----
    if (MODE == 1) {
        for (int i = tid; i < 8 * KP; i += 256) {
            int r = i / KP, k = i - r * KP;
            s_a[r][k] = (k < SD) ? g_feats[(r0 + r) * SD + k] : 0.0f;
        }
    } else {
        const float* Zin = (MODE == 2) ? g_z1 : g_z2;
        const float* zr = Zin + (r0 + row) * HID;   // warp `row` handles its row
        float v[16];
        float sum = 0.0f;
        #pragma unroll
        for (int i = 0; i < 16; i++) { v[i] = zr[col + 32 * i]; sum += v[i]; }
        #pragma unroll
        for (int o = 16; o; o >>= 1) sum += __shfl_xor_sync(0xffffffffu, sum, o);
        float mu = sum * (1.0f / 512.0f);
        float vs = 0.0f;
        #pragma unroll
        for (int i = 0; i < 16; i++) { float d = v[i] - mu; vs += d * d; }
        #pragma unroll
        for (int o = 16; o; o >>= 1) vs += __shfl_xor_sync(0xffffffffu, vs, o);
        float rstd = rsqrtf(vs * (1.0f / 512.0f) + 1e-5f);
        #pragma unroll
        for (int i = 0; i < 16; i++) {
            int k = col + 32 * i;
            float hv = (v[i] - mu) * rstd * g[k] + be[k];
            s_a[row][k] = fmaxf(hv, 0.0f);
        }
    }

    // ---- W prefetch helpers: chunk = 64 rows x 32 cols, 2 float4 / thread --
    const int krow0 = tid >> 3;            // element tid
    const int c4_0  = (tid & 7) << 2;
    const int krow1 = (tid + 256) >> 3;    // element tid+256
    const int c4_1  = c4_0;                // (e&7) identical for e and e+256

    float4 p0, p1;
    // prefetch chunk 0
    {
        int ka = krow0, kb = krow1;
        if (MODE == 1 && ka >= SD) p0 = make_float4(0, 0, 0, 0);
        else p0 = *(const float4*)&W[(long)ka * N + c0 + c4_0];
        if (MODE == 1 && kb >= SD) p1 = make_float4(0, 0, 0, 0);
        else p1 = *(const float4*)&W[(long)kb * N + c0 + c4_1];
    }
    *(float4*)&s_w[0][krow0][c4_0] = p0;
    *(float4*)&s_w[0][krow1][c4_1] = p1;

    float acc = 0.0f;
    #pragma unroll
    for (int c = 0; c < NC; c++) {
        if (c + 1 < NC) {
            int ka = (c + 1) * 64 + krow0;
            int kb = (c + 1) * 64 + krow1;
            if (MODE == 1 && ka >= SD) p0 = make_float4(0, 0, 0, 0);
            else p0 = *(const float4*)&W[(long)ka * N + c0 + c4_0];
            if (MODE == 1 && kb >= SD) p1 = make_float4(0, 0, 0, 0);
            else p1 = *(const float4*)&W[(long)kb * N + c0 + c4_1];
        }
        __syncthreads();
        const int bsel = c & 1;
        #pragma unroll
        for (int kk = 0; kk < 64; kk++)
            acc = fmaf(s_a[row][c * 64 + kk], s_w[bsel][kk][col], acc);
        if (c + 1 < NC) {
            *(float4*)&s_w[bsel ^ 1][krow0][c4_0] = p0;
            *(float4*)&s_w[bsel ^ 1][krow1][c4_1] = p1;
        }
    }

    const int cg = c0 + col;
    float r_ = acc + bias[cg];
    if (MODE == 1)       g_z1[(r0 + row) * HID + cg] = r_;
    else if (MODE == 2)  g_z2[(r0 + row) * HID + cg] = r_;
    else                 outp[(r0 + row) * DM + cg] = r_;
}

// ---------------- launch ----------------------------------------------------
extern "C" void kernel_launch(void* const* d_in, const int* in_sizes, int n_in,
                              void* d_out, int out_size) {
    const int*   x   = (const int*)d_in[0];
    const float* W1  = (const float*)d_in[1];
    const float* b1  = (const float*)d_in[2];
    const float* g1  = (const float*)d_in[3];
    const float* be1 = (const float*)d_in[4];
    const float* W2  = (const float*)d_in[5];
    const float* b2  = (const float*)d_in[6];
    const float* g2  = (const float*)d_in[7];
    const float* be2 = (const float*)d_in[8];
    const float* W3  = (const float*)d_in[9];
    const float* b3  = (const float*)d_in[10];
    float* out = (float*)d_out;

    win_kernel<<<dim3(BPB, BB), 256>>>(x);
    feat_kernel<<<BB, 256>>>();
    mlp_kernel<1><<<dim3(HID / 32, BB / 8), 256>>>(nullptr, nullptr, W1, b1, nullptr);
    mlp_kernel<2><<<dim3(HID / 32, BB / 8), 256>>>(g1, be1, W2, b2, nullptr);
    mlp_kernel<3><<<dim3(DM / 32, BB / 8), 256>>>(g2, be2, W3, b3, out);
}

// round 3
// speedup vs baseline: 2.1858x; 1.1990x over previous
#include <cuda_runtime.h>
#include <cuda_bf16.h>
#include <math.h>

#define BB   64
#define LL   65536
#define NW   2047
#define WPB  128
#define BPB  16
#define SPAN_MAX 4128
#define HID  512
#define DM   256
#define SD   321

// ---------------- scratch (__device__ globals; no allocation allowed) -------
__device__ unsigned int g_hist_parts[BB * BPB * 256];
__device__ float g_went[BB * NW];
__device__ float g_feats[BB * SD];
__device__ float g_z1p[3][BB * HID];   // layer-1 split-K partials
__device__ float g_z2p[4][BB * HID];   // layer-2 split-K partials
__device__ float g_outp[4][BB * DM];   // layer-3 split-K partials

// ---------------- Kernel A: windowed entropies + global hist partials -------
__global__ void __launch_bounds__(256) win_kernel(const int* __restrict__ x) {
    const int b    = blockIdx.y;
    const int blk  = blockIdx.x;
    const int tid  = threadIdx.x;
    const int lane = tid & 31;
    const int warp = tid >> 5;

    const int wstart = blk * WPB;
    const int wcount = min(WPB, NW - wstart);
    const int span   = (wcount - 1) * 32 + 64;
    const long base  = (long)b * LL + (long)blk * (WPB * 32);

    __shared__ __align__(16) unsigned char s_x[SPAN_MAX + 32];
    __shared__ unsigned int  s_hist[8][256];
    __shared__ unsigned int  s_part[256];
    __shared__ float         s_lut[65];

    if (tid < 256) s_part[tid] = 0u;
    if (tid <= 64) {
        if (tid == 0) s_lut[0] = 0.0f;
        else {
            float p = (float)tid * (1.0f / 64.0f);
            float t = -(p * log2f(p + 1e-10f));
            s_lut[tid] = t / (float)tid;
        }
    }
    {
        const int4* xv = (const int4*)(x + base);
        uchar4* sv = (uchar4*)s_x;
        const int n4 = span >> 2;
        for (int i = tid; i < n4; i += 256) {
            int4 v = xv[i];
            sv[i] = make_uchar4((unsigned char)min(max(v.x, 0), 255),
                                (unsigned char)min(max(v.y, 0), 255),
                                (unsigned char)min(max(v.z, 0), 255),
                                (unsigned char)min(max(v.w, 0), 255));
        }
    }
    __syncthreads();

    for (int i = tid; i < 4096; i += 256)
        atomicAdd(&s_part[s_x[i]], 1u);

    unsigned int* hist = s_hist[warp];
    for (int wi = warp; wi < wcount; wi += 8) {
        const int off = wi * 32;
        #pragma unroll
        for (int j = 0; j < 8; j++) hist[lane + 32 * j] = 0u;
        __syncwarp();
        const int va = s_x[off + lane];
        const int vb = s_x[off + 32 + lane];
        atomicAdd(&hist[va], 1u);
        atomicAdd(&hist[vb], 1u);
        __syncwarp();
        float h = s_lut[hist[va]] + s_lut[hist[vb]];
        #pragma unroll
        for (int o = 16; o; o >>= 1) h += __shfl_xor_sync(0xffffffffu, h, o);
        if (lane == 0) g_went[b * NW + wstart + wi] = h;
    }

    __syncthreads();
    if (tid < 256) g_hist_parts[(b * BPB + blk) * 256 + tid] = s_part[tid];
}

// ---------------- Kernel B: features -----------------------------------------
__global__ void __launch_bounds__(256) feat_kernel() {
    const int b = blockIdx.x;
    const int tid = threadIdx.x;

    __shared__ float        s_red[256];
    __shared__ float        s_lev[64];
    __shared__ unsigned int s_cnt[64];

    float term = 0.0f;
    {
        unsigned int c = 0;
        #pragma unroll
        for (int p = 0; p < BPB; p++)
            c += g_hist_parts[(b * BPB + p) * 256 + tid];
        float nh = (float)c * (1.0f / 65536.0f);
        g_feats[b * SD + tid] = nh;
        term = -(nh * log2f(nh + 1e-10f));
    }
    s_red[tid] = term;
    if (tid < 64) {
        s_lev[tid] = (tid == 63) ? 8.0f : (float)tid * (8.0f / 63.0f);
        s_cnt[tid] = 0u;
    }
    __syncthreads();

    for (int s = 128; s; s >>= 1) {
        if (tid < s) s_red[tid] += s_red[tid + s];
        __syncthreads();
    }
    if (tid == 0) g_feats[b * SD + 256] = s_red[0];

    for (int i = tid; i < NW; i += 256) {
        float h = g_went[b * NW + i];
        int lo = 0, hi = 63;
        while (lo < hi) {
            int mid = (lo + hi) >> 1;
            if (h <= s_lev[mid]) hi = mid; else lo = mid + 1;
        }
        atomicAdd(&s_cnt[lo], 1u);
    }
    __syncthreads();
    if (tid < 64) {
        unsigned int sum = 0;
        for (int k = 0; k <= tid; k++) sum += s_cnt[k];
        g_feats[b * SD + 257 + tid] = (float)sum / 2047.0f;
    }
}

// ---------------- Split-K MLP GEMMs ------------------------------------------
// Block: 128 threads (4 warps). Tile: 8 rows x 64 cols x Kc=128.
// Warp w -> rows {2w, 2w+1}; lane -> cols {2*lane, 2*lane+1}. 2x2 reg tile.
// MODE 1: A = feats (K=321, S=3 chunks), writes g_z1p[ks]
// MODE 2: A = relu(LN(sum g_z1p + b1)), K=512, S=4, writes g_z2p[ks]
// MODE 3: A = relu(LN(sum g_z2p + b2)), K=512, S=4, N=256, writes g_outp[ks]
template <int MODE>
__global__ void __launch_bounds__(128) mlp_kernel(const float* __restrict__ gam,
                                                  const float* __restrict__ bet,
                                                  const float* __restrict__ bprev,
                                                  const float* __restrict__ W) {
    constexpr int K  = (MODE == 1) ? SD : HID;
    constexpr int Sp = (MODE == 2) ? 3 : 4;          // prev-layer partial count
    constexpr int N  = (MODE == 3) ? DM : HID;

    const int tid  = threadIdx.x;
    const int lane = tid & 31;
    const int w    = tid >> 5;
    const int c0   = blockIdx.x * 64;
    const int r0   = blockIdx.y * 8;
    const int k0   = blockIdx.z * 128;
    const int ks   = blockIdx.z;

    __shared__ float s_w[128][64];
    __shared__ float s_a[128][10];    // transposed A slice, padded

    // ---- W chunk: 128 rows x 64 cols, 16 float4 per thread, coalesced ----
    {
        const int rbase = tid >> 4;
        const int col4  = (tid & 15) * 4;
        #pragma unroll
        for (int i = 0; i < 16; i++) {
            const int kr = rbase + i * 8;
            float4 v;
            if (MODE != 1 || (k0 + kr) < K)
                v = *(const float4*)&W[(long)(k0 + kr) * N + c0 + col4];
            else
                v = make_float4(0.f, 0.f, 0.f, 0.f);
            *(float4*)&s_w[kr][col4] = v;
        }
    }

    // ---- A stage ----
    if (MODE == 1) {
        for (int i = tid; i < 128 * 8; i += 128) {
            const int kk = i >> 3, r = i & 7;
            const int k = k0 + kk;
            s_a[kk][r] = (k < K) ? g_feats[(r0 + r) * SD + k] : 0.0f;
        }
    } else {
        const float* P = (MODE == 2) ? &g_z1p[0][0] : &g_z2p[0][0];
        #pragma unroll
        for (int rr = 0; rr < 2; rr++) {
            const int r = r0 + w * 2 + rr;
            float v[16];
            float sum = 0.0f;
            #pragma unroll
            for (int i = 0; i < 16; i++) {
                const int k = lane + 32 * i;
                float z = bprev[k];
                #pragma unroll
                for (int s = 0; s < Sp; s++) z += P[s * (BB * HID) + r * HID + k];
                v[i] = z; sum += z;
            }
            #pragma unroll
            for (int o = 16; o; o >>= 1) sum += __shfl_xor_sync(0xffffffffu, sum, o);
            const float mu = sum * (1.0f / 512.0f);
            float vs = 0.0f;
            #pragma unroll
            for (int i = 0; i < 16; i++) { const float d = v[i] - mu; vs += d * d; }
            #pragma unroll
            for (int o = 16; o; o >>= 1) vs += __shfl_xor_sync(0xffffffffu, vs, o);
            const float rstd = rsqrtf(vs * (1.0f / 512.0f) + 1e-5f);
            #pragma unroll
            for (int i = 0; i < 4; i++) {
                const int ii = (k0 >> 5) + i;
                const int k = lane + 32 * ii;
                const float hv = (v[ii] - mu) * rstd * gam[k] + bet[k];
                s_a[k - k0][w * 2 + rr] = fmaxf(hv, 0.0f);
            }
        }
    }
    __syncthreads();

    // ---- compute: 2x2 register tile, 4 independent chains ----
    float a00 = 0.f, a01 = 0.f, a10 = 0.f, a11 = 0.f;
    const int cl = lane * 2;
    #pragma unroll 8
    for (int kk = 0; kk < 128; kk++) {
        const float2 wv = *(const float2*)&s_w[kk][cl];
        const float2 av = *(const float2*)&s_a[kk][w * 2];
        a00 = fmaf(av.x, wv.x, a00);
        a01 = fmaf(av.x, wv.y, a01);
        a10 = fmaf(av.y, wv.x, a10);
        a11 = fmaf(av.y, wv.y, a11);
    }

    // ---- write split-K partials ----
    float* OP = (MODE == 1) ? &g_z1p[0][0] : (MODE == 2) ? &g_z2p[0][0] : &g_outp[0][0];
    const int bufsz = BB * N;
    const int r = r0 + w * 2;
    const int c = c0 + cl;
    OP[ks * bufsz + r * N + c]           = a00;
    OP[ks * bufsz + r * N + c + 1]       = a01;
    OP[ks * bufsz + (r + 1) * N + c]     = a10;
    OP[ks * bufsz + (r + 1) * N + c + 1] = a11;
}

// ---------------- finalize: out = sum(g_outp) + b3 ---------------------------
__global__ void __launch_bounds__(256) fin_kernel(const float* __restrict__ b3,
                                                  float* __restrict__ out) {
    const int i = blockIdx.x * 256 + threadIdx.x;
    float v = b3[i & (DM - 1)];
    #pragma unroll
    for (int s = 0; s < 4; s++) v += g_outp[s][i];
    out[i] = v;
}

// ---------------- launch ----------------------------------------------------
extern "C" void kernel_launch(void* const* d_in, const int* in_sizes, int n_in,
                              void* d_out, int out_size) {
    const int*   x   = (const int*)d_in[0];
    const float* W1  = (const float*)d_in[1];
    const float* b1  = (const float*)d_in[2];
    const float* g1  = (const float*)d_in[3];
    const float* be1 = (const float*)d_in[4];
    const float* W2  = (const float*)d_in[5];
    const float* b2  = (const float*)d_in[6];
    const float* g2  = (const float*)d_in[7];
    const float* be2 = (const float*)d_in[8];
    const float* W3  = (const float*)d_in[9];
    const float* b3  = (const float*)d_in[10];
    float* out = (float*)d_out;

    win_kernel<<<dim3(BPB, BB), 256>>>(x);
    feat_kernel<<<BB, 256>>>();
    mlp_kernel<1><<<dim3(8, 8, 3), 128>>>(nullptr, nullptr, nullptr, W1);
    mlp_kernel<2><<<dim3(8, 8, 4), 128>>>(g1, be1, b1, W2);
    mlp_kernel<3><<<dim3(4, 8, 4), 128>>>(g2, be2, b2, W3);
    fin_kernel<<<(BB * DM) / 256, 256>>>(b3, out);
}

// round 5
// speedup vs baseline: 2.3015x; 1.0529x over previous
#include <cuda_runtime.h>
#include <cuda_bf16.h>
#include <math.h>

#define BB   64
#define LL   65536
#define NW   2047
#define WPB  128
#define BPB  16
#define SPAN_MAX 4128
#define HID  512
#define DM   256
#define SD   321

// ---------------- scratch (__device__ globals; no allocation allowed) -------
__device__ unsigned int g_hist_parts[BB * BPB * 256];
__device__ float g_went[BB * NW];
__device__ float g_feats[BB * SD];
__device__ float g_z1p[6][BB * HID];   // layer-1 split-K partials
__device__ float g_z2p[8][BB * HID];   // layer-2 split-K partials
__device__ float g_outp[8][BB * DM];   // layer-3 split-K partials
__device__ float g_a2[BB * HID];       // relu(LN(z1)) activations
__device__ float g_a3[BB * HID];       // relu(LN(z2)) activations

// ---------------- Kernel A: windowed entropies + global hist partials -------
__global__ void __launch_bounds__(256) win_kernel(const int* __restrict__ x) {
    const int b    = blockIdx.y;
    const int blk  = blockIdx.x;
    const int tid  = threadIdx.x;
    const int lane = tid & 31;
    const int warp = tid >> 5;

    const int wstart = blk * WPB;
    const int wcount = min(WPB, NW - wstart);
    const int span   = (wcount - 1) * 32 + 64;
    const long base  = (long)b * LL + (long)blk * (WPB * 32);

    __shared__ __align__(16) unsigned char s_x[SPAN_MAX + 32];
    __shared__ unsigned int  s_hist[8][64];   // packed u8 counts (4 per word)
    __shared__ unsigned int  s_part[256];
    __shared__ float         s_lut[65];

    if (tid < 256) s_part[tid] = 0u;
    if (tid <= 64) {
        if (tid == 0) s_lut[0] = 0.0f;
        else {
            float p = (float)tid * (1.0f / 64.0f);
            float t = -(p * log2f(p + 1e-10f));
            s_lut[tid] = t / (float)tid;
        }
    }
    {
        const int4* xv = (const int4*)(x + base);
        uchar4* sv = (uchar4*)s_x;
        const int n4 = span >> 2;
        for (int i = tid; i < n4; i += 256) {
            int4 v = xv[i];
            sv[i] = make_uchar4((unsigned char)min(max(v.x, 0), 255),
                                (unsigned char)min(max(v.y, 0), 255),
                                (unsigned char)min(max(v.z, 0), 255),
                                (unsigned char)min(max(v.w, 0), 255));
        }
    }
    __syncthreads();

    for (int i = tid; i < 4096; i += 256)
        atomicAdd(&s_part[s_x[i]], 1u);

    unsigned int* hist = s_hist[warp];
    for (int wi = warp; wi < wcount; wi += 8) {
        const int off = wi * 32;
        hist[lane]      = 0u;
        hist[lane + 32] = 0u;
        __syncwarp();
        const int va = s_x[off + lane];
        const int vb = s_x[off + 32 + lane];
        atomicAdd(&hist[va >> 2], 1u << ((va & 3) << 3));
        atomicAdd(&hist[vb >> 2], 1u << ((vb & 3) << 3));
        __syncwarp();
        const unsigned ca = (hist[va >> 2] >> ((va & 3) << 3)) & 0xFFu;
        const unsigned cb = (hist[vb >> 2] >> ((vb & 3) << 3)) & 0xFFu;
        float h = s_lut[ca] + s_lut[cb];
        #pragma unroll
        for (int o = 16; o; o >>= 1) h += __shfl_xor_sync(0xffffffffu, h, o);
        if (lane == 0) g_went[b * NW + wstart + wi] = h;
    }

    __syncthreads();
    if (tid < 256) g_hist_parts[(b * BPB + blk) * 256 + tid] = s_part[tid];
}

// ---------------- Kernel B: features -----------------------------------------
__global__ void __launch_bounds__(256) feat_kernel() {
    const int b = blockIdx.x;
    const int tid = threadIdx.x;

    __shared__ float        s_red[256];
    __shared__ float        s_lev[64];
    __shared__ unsigned int s_cnt[64];

    float term = 0.0f;
    {
        unsigned int c = 0;
        #pragma unroll
        for (int p = 0; p < BPB; p++)
            c += g_hist_parts[(b * BPB + p) * 256 + tid];
        float nh = (float)c * (1.0f / 65536.0f);
        g_feats[b * SD + tid] = nh;
        term = -(nh * log2f(nh + 1e-10f));
    }
    s_red[tid] = term;
    if (tid < 64) {
        s_lev[tid] = (tid == 63) ? 8.0f : (float)tid * (8.0f / 63.0f);
        s_cnt[tid] = 0u;
    }
    __syncthreads();

    for (int s = 128; s; s >>= 1) {
        if (tid < s) s_red[tid] += s_red[tid + s];
        __syncthreads();
    }
    if (tid == 0) g_feats[b * SD + 256] = s_red[0];

    for (int i = tid; i < NW; i += 256) {
        float h = g_went[b * NW + i];
        int lo = 0, hi = 63;
        while (lo < hi) {
            int mid = (lo + hi) >> 1;
            if (h <= s_lev[mid]) hi = mid; else lo = mid + 1;
        }
        atomicAdd(&s_cnt[lo], 1u);
    }
    __syncthreads();
    if (tid < 64) {
        unsigned int sum = 0;
        for (int k = 0; k <= tid; k++) sum += s_cnt[k];
        g_feats[b * SD + 257 + tid] = (float)sum / 2047.0f;
    }
}

// ---------------- Split-K GEMM: pure matmul partials -------------------------
// Block 128 thr (4 warps). Tile: 8 rows x 128 cols x 64 k. Thread: 2x4 tile.
// MODE 1: A=g_feats (K=321), N=512 -> g_z1p[6]
// MODE 2: A=g_a2 (K=512),   N=512 -> g_z2p[8]
// MODE 3: A=g_a3 (K=512),   N=256 -> g_outp[8]
template <int MODE>
__global__ void __launch_bounds__(128) gemm_kernel(const float* __restrict__ W) {
    constexpr int N = (MODE == 3) ? DM : HID;
    constexpr int K = (MODE == 1) ? SD : HID;

    const int tid  = threadIdx.x;
    const int lane = tid & 31;
    const int w    = tid >> 5;
    const int c0   = blockIdx.x * 128;
    const int r0   = blockIdx.y * 8;
    const int k0   = blockIdx.z * 64;
    const int ks   = blockIdx.z;

    __shared__ float s_w[64][128];
    __shared__ float s_a[64][10];

    // W chunk: 64 rows x 128 cols, 16 float4 per thread, coalesced
    {
        const int kr0 = tid >> 5;            // 0..3
        const int c4  = (tid & 31) * 4;
        #pragma unroll
        for (int i = 0; i < 16; i++) {
            const int kr = kr0 + i * 4;
            float4 v = make_float4(0.f, 0.f, 0.f, 0.f);
            if (MODE != 1 || (k0 + kr) < K)
                v = *(const float4*)&W[(long)(k0 + kr) * N + c0 + c4];
            *(float4*)&s_w[kr][c4] = v;
        }
    }
    // A slice: 8 rows x 64 k, transposed into s_a[k][r]
    {
        const float* A   = (MODE == 1) ? g_feats : ((MODE == 2) ? g_a2 : g_a3);
        const int astr   = (MODE == 1) ? SD : HID;
        for (int i = tid; i < 512; i += 128) {
            const int r = i >> 6, k = i & 63;
            float v = 0.f;
            if (MODE != 1 || (k0 + k) < K) v = A[(r0 + r) * astr + k0 + k];
            s_a[k][r] = v;
        }
    }
    __syncthreads();

    float a0x = 0.f, a0y = 0.f, a0z = 0.f, a0w = 0.f;
    float a1x = 0.f, a1y = 0.f, a1z = 0.f, a1w = 0.f;
    const int cl = lane * 4;
    #pragma unroll 16
    for (int kk = 0; kk < 64; kk++) {
        const float4 wv = *(const float4*)&s_w[kk][cl];
        const float2 av = *(const float2*)&s_a[kk][w * 2];
        a0x = fmaf(av.x, wv.x, a0x);
        a0y = fmaf(av.x, wv.y, a0y);
        a0z = fmaf(av.x, wv.z, a0z);
        a0w = fmaf(av.x, wv.w, a0w);
        a1x = fmaf(av.y, wv.x, a1x);
        a1y = fmaf(av.y, wv.y, a1y);
        a1z = fmaf(av.y, wv.z, a1z);
        a1w = fmaf(av.y, wv.w, a1w);
    }

    float* OP = (MODE == 1) ? &g_z1p[0][0] : ((MODE == 2) ? &g_z2p[0][0] : &g_outp[0][0]);
    const long base = (long)ks * (BB * N);
    const int r = r0 + w * 2;
    const int c = c0 + cl;
    *(float4*)&OP[base + (long)r * N + c]       = make_float4(a0x, a0y, a0z, a0w);
    *(float4*)&OP[base + (long)(r + 1) * N + c] = make_float4(a1x, a1y, a1z, a1w);
}

// ---------------- reduce + bias + LN + ReLU ----------------------------------
// LAYER 1: sum g_z1p[6] + b1 -> LN -> relu -> g_a2
// LAYER 2: sum g_z2p[8] + b2 -> LN -> relu -> g_a3
// grid 64 (one block per row), block 512 (one thread per feature)
template <int LAYER>
__global__ void __launch_bounds__(512) red_ln_kernel(const float* __restrict__ bias,
                                                     const float* __restrict__ gam,
                                                     const float* __restrict__ bet) {
    constexpr int SP = (LAYER == 1) ? 6 : 8;
    const float* P   = (LAYER == 1) ? &g_z1p[0][0] : &g_z2p[0][0];
    float* outA      = (LAYER == 1) ? g_a2 : g_a3;

    const int r = blockIdx.x;
    const int k = threadIdx.x;
    const int lane = k & 31;
    const int wid  = k >> 5;

    __shared__ float s_r[16];
    __shared__ float s_tot;

    float z = bias[k];
    #pragma unroll
    for (int s = 0; s < SP; s++) z += P[(long)s * (BB * HID) + r * HID + k];

    float t = z;
    #pragma unroll
    for (int o = 16; o; o >>= 1) t += __shfl_xor_sync(0xffffffffu, t, o);
    if (lane == 0) s_r[wid] = t;
    __syncthreads();
    if (wid == 0) {
        float u = s_r[lane & 15];
        #pragma unroll
        for (int o = 8; o; o >>= 1) u += __shfl_xor_sync(0xffffffffu, u, o);
        if (lane == 0) s_tot = u;
    }
    __syncthreads();
    const float mu = s_tot * (1.0f / 512.0f);

    const float d = z - mu;
    float v = d * d;
    #pragma unroll
    for (int o = 16; o; o >>= 1) v += __shfl_xor_sync(0xffffffffu, v, o);
    if (lane == 0) s_r[wid] = v;
    __syncthreads();
    if (wid == 0) {
        float u = s_r[lane & 15];
        #pragma unroll
        for (int o = 8; o; o >>= 1) u += __shfl_xor_sync(0xffffffffu, u, o);
        if (lane == 0) s_tot = u;
    }
    __syncthreads();
    const float rstd = rsqrtf(s_tot * (1.0f / 512.0f) + 1e-5f);

    outA[r * HID + k] = fmaxf(d * rstd * gam[k] + bet[k], 0.0f);
}

// ---------------- finalize: out = sum(g_outp) + b3 ---------------------------
__global__ void __launch_bounds__(256) fin_kernel(const float* __restrict__ b3,
                                                  float* __restrict__ out) {
    const int i = blockIdx.x * 256 + threadIdx.x;
    float v = b3[i & (DM - 1)];
    #pragma unroll
    for (int s = 0; s < 8; s++) v += g_outp[s][i];
    out[i] = v;
}

// ---------------- launch ----------------------------------------------------
extern "C" void kernel_launch(void* const* d_in, const int* in_sizes, int n_in,
                              void* d_out, int out_size) {
    const int*   x   = (const int*)d_in[0];
    const float* W1  = (const float*)d_in[1];
    const float* b1  = (const float*)d_in[2];
    const float* g1  = (const float*)d_in[3];
    const float* be1 = (const float*)d_in[4];
    const float* W2  = (const float*)d_in[5];
    const float* b2  = (const float*)d_in[6];
    const float* g2  = (const float*)d_in[7];
    const float* be2 = (const float*)d_in[8];
    const float* W3  = (const float*)d_in[9];
    const float* b3  = (const float*)d_in[10];
    float* out = (float*)d_out;

    win_kernel<<<dim3(BPB, BB), 256>>>(x);
    feat_kernel<<<BB, 256>>>();
    gemm_kernel<1><<<dim3(4, 8, 6), 128>>>(W1);
    red_ln_kernel<1><<<BB, 512>>>(b1, g1, be1);
    gemm_kernel<2><<<dim3(4, 8, 8), 128>>>(W2);
    red_ln_kernel<2><<<BB, 512>>>(b2, g2, be2);
    gemm_kernel<3><<<dim3(2, 8, 8), 128>>>(W3);
    fin_kernel<<<(BB * DM) / 256, 256>>>(b3, out);
}